// round 1
// baseline (speedup 1.0000x reference)
#include <cuda_runtime.h>
#include <math.h>

#define N_TOKENS 4096
#define HID      1024
#define FFN      2048
#define NEXP     8
#define TOPK     2
#define NPAIR    (N_TOKENS * TOPK)   // 8192

// ---------------- device scratch (no allocs allowed) ----------------
__device__ float g_h[(size_t)NPAIR * FFN];   // 64 MB: gelu(x @ w1_e), bucketed rows
__device__ float g_y[(size_t)NPAIR * HID];   // 32 MB: expert outputs, bucketed rows
__device__ int   g_rowmap[NPAIR];            // pos -> token
__device__ int   g_posof[NPAIR];             // pair(token*2+k) -> pos
__device__ int   g_topk_idx[NPAIR];
__device__ float g_topk_prob[NPAIR];
__device__ int   g_counts[NEXP];
__device__ int   g_counts2[NEXP];
__device__ int   g_offsets[NEXP + 1];

__device__ __forceinline__ float gelu_exact(float v) {
    return 0.5f * v * (1.0f + erff(v * 0.70710678118654752f));
}

// ---------------- init: zero counters (every graph replay) ----------------
__global__ void init_kernel() {
    int i = threadIdx.x;
    if (i < NEXP) { g_counts[i] = 0; g_counts2[i] = 0; }
}

// ---------------- router: logits, softmax, top-2 ----------------
// 1 block per token, 8 warps: warp w computes logit for expert w.
__global__ void router_kernel(const float* __restrict__ x,
                              const float* __restrict__ rw) {
    int t    = blockIdx.x;
    int tid  = threadIdx.x;
    int w    = tid >> 5;
    int lane = tid & 31;
    const float* xr = x + (size_t)t * HID;
    float s = 0.f;
#pragma unroll 8
    for (int i = lane; i < HID; i += 32)
        s += xr[i] * rw[i * NEXP + w];
#pragma unroll
    for (int o = 16; o; o >>= 1) s += __shfl_xor_sync(0xffffffffu, s, o);

    __shared__ float logits[NEXP];
    if (lane == 0) logits[w] = s;
    __syncthreads();

    if (tid == 0) {
        float mx = logits[0];
#pragma unroll
        for (int e = 1; e < NEXP; e++) mx = fmaxf(mx, logits[e]);
        float p[NEXP];
        float den = 0.f;
#pragma unroll
        for (int e = 0; e < NEXP; e++) { p[e] = expf(logits[e] - mx); den += p[e]; }
        // top-2, lowest-index tie-break (matches jax.lax.top_k)
        int i0 = 0;
#pragma unroll
        for (int e = 1; e < NEXP; e++) if (p[e] > p[i0]) i0 = e;
        int i1 = (i0 == 0) ? 1 : 0;
#pragma unroll
        for (int e = 0; e < NEXP; e++) if (e != i0 && p[e] > p[i1]) i1 = e;
        float inv = 1.f / den;
        g_topk_idx[2 * t]      = i0;
        g_topk_idx[2 * t + 1]  = i1;
        g_topk_prob[2 * t]     = p[i0] * inv;
        g_topk_prob[2 * t + 1] = p[i1] * inv;
        atomicAdd(&g_counts[i0], 1);
        atomicAdd(&g_counts[i1], 1);
    }
}

// ---------------- offsets: tiny exclusive scan over 8 experts ----------------
__global__ void offsets_kernel() {
    int o = 0;
#pragma unroll
    for (int e = 0; e < NEXP; e++) { g_offsets[e] = o; o += g_counts[e]; }
    g_offsets[NEXP] = o;   // == NPAIR
}

// ---------------- scatter: bucket pairs by expert ----------------
__global__ void scatter_kernel() {
    int p = blockIdx.x * blockDim.x + threadIdx.x;
    if (p >= NPAIR) return;
    int e   = g_topk_idx[p];
    int pos = g_offsets[e] + atomicAdd(&g_counts2[e], 1);
    g_rowmap[pos] = p >> 1;
    g_posof[p]    = pos;
}

// ---------------- grouped GEMM 1: h = gelu(x_gathered @ w1_e) ----------------
// C tile 64x64, BK=16, 256 threads, 4x4 micro-tile, float4 smem fragments.
__global__ __launch_bounds__(256) void gemm1_kernel(const float* __restrict__ x,
                                                    const float* __restrict__ w1) {
    const int e     = blockIdx.z;
    const int start = g_offsets[e];
    const int end   = g_offsets[e + 1];
    const int m0    = start + blockIdx.y * 64;
    if (m0 >= end) return;
    const int n0 = blockIdx.x * 64;

    __shared__ __align__(16) float As[16][68];
    __shared__ __align__(16) float Bs[16][64];

    const int tid = threadIdx.x;
    const int tx  = tid & 15;
    const int ty  = tid >> 4;

    // A loader: thread -> (row, 4 consecutive k)
    const int arow = tid >> 2;
    const int ak   = (tid & 3) * 4;
    const int r    = m0 + arow;
    const int token = g_rowmap[(r < end) ? r : start];
    const float* aptr = x + (size_t)token * HID + ak;

    // B loader: thread -> (k row, 4 consecutive n). w1 row stride = NEXP*FFN.
    const int bk = tid >> 4;
    const int bn = (tid & 15) * 4;
    const float* bptr = w1 + (size_t)e * FFN + n0 + bn;

    float acc[4][4];
#pragma unroll
    for (int i = 0; i < 4; i++)
#pragma unroll
        for (int j = 0; j < 4; j++) acc[i][j] = 0.f;

    for (int kt = 0; kt < HID; kt += 16) {
        float4 av = *(const float4*)(aptr + kt);
        float4 bv = *(const float4*)(bptr + (size_t)(kt + bk) * (NEXP * FFN));
        As[ak + 0][arow] = av.x;
        As[ak + 1][arow] = av.y;
        As[ak + 2][arow] = av.z;
        As[ak + 3][arow] = av.w;
        *(float4*)&Bs[bk][bn] = bv;
        __syncthreads();
#pragma unroll
        for (int kk = 0; kk < 16; kk++) {
            float4 a = *(const float4*)&As[kk][ty * 4];
            float4 b = *(const float4*)&Bs[kk][tx * 4];
            acc[0][0] += a.x * b.x; acc[0][1] += a.x * b.y; acc[0][2] += a.x * b.z; acc[0][3] += a.x * b.w;
            acc[1][0] += a.y * b.x; acc[1][1] += a.y * b.y; acc[1][2] += a.y * b.z; acc[1][3] += a.y * b.w;
            acc[2][0] += a.z * b.x; acc[2][1] += a.z * b.y; acc[2][2] += a.z * b.z; acc[2][3] += a.z * b.w;
            acc[3][0] += a.w * b.x; acc[3][1] += a.w * b.y; acc[3][2] += a.w * b.z; acc[3][3] += a.w * b.w;
        }
        __syncthreads();
    }

#pragma unroll
    for (int i = 0; i < 4; i++) {
        int rr = m0 + ty * 4 + i;
        if (rr < end) {
            float4 o;
            o.x = gelu_exact(acc[i][0]);
            o.y = gelu_exact(acc[i][1]);
            o.z = gelu_exact(acc[i][2]);
            o.w = gelu_exact(acc[i][3]);
            *(float4*)&g_h[(size_t)rr * FFN + n0 + tx * 4] = o;
        }
    }
}

// ---------------- grouped GEMM 2: y = h @ w2_e ----------------
__global__ __launch_bounds__(256) void gemm2_kernel(const float* __restrict__ w2) {
    const int e     = blockIdx.z;
    const int start = g_offsets[e];
    const int end   = g_offsets[e + 1];
    const int m0    = start + blockIdx.y * 64;
    if (m0 >= end) return;
    const int n0 = blockIdx.x * 64;

    __shared__ __align__(16) float As[16][68];
    __shared__ __align__(16) float Bs[16][64];

    const int tid = threadIdx.x;
    const int tx  = tid & 15;
    const int ty  = tid >> 4;

    const int arow = tid >> 2;
    const int ak   = (tid & 3) * 4;
    const int r    = m0 + arow;
    const int rsafe = (r < end) ? r : start;
    const float* aptr = g_h + (size_t)rsafe * FFN + ak;

    const int bk = tid >> 4;
    const int bn = (tid & 15) * 4;
    // w2 slice for expert e: rows [e*FFN, (e+1)*FFN), row stride HID
    const float* bptr = w2 + (size_t)e * FFN * HID + n0 + bn;

    float acc[4][4];
#pragma unroll
    for (int i = 0; i < 4; i++)
#pragma unroll
        for (int j = 0; j < 4; j++) acc[i][j] = 0.f;

    for (int kt = 0; kt < FFN; kt += 16) {
        float4 av = *(const float4*)(aptr + kt);
        float4 bv = *(const float4*)(bptr + (size_t)(kt + bk) * HID);
        As[ak + 0][arow] = av.x;
        As[ak + 1][arow] = av.y;
        As[ak + 2][arow] = av.z;
        As[ak + 3][arow] = av.w;
        *(float4*)&Bs[bk][bn] = bv;
        __syncthreads();
#pragma unroll
        for (int kk = 0; kk < 16; kk++) {
            float4 a = *(const float4*)&As[kk][ty * 4];
            float4 b = *(const float4*)&Bs[kk][tx * 4];
            acc[0][0] += a.x * b.x; acc[0][1] += a.x * b.y; acc[0][2] += a.x * b.z; acc[0][3] += a.x * b.w;
            acc[1][0] += a.y * b.x; acc[1][1] += a.y * b.y; acc[1][2] += a.y * b.z; acc[1][3] += a.y * b.w;
            acc[2][0] += a.z * b.x; acc[2][1] += a.z * b.y; acc[2][2] += a.z * b.z; acc[2][3] += a.z * b.w;
            acc[3][0] += a.w * b.x; acc[3][1] += a.w * b.y; acc[3][2] += a.w * b.z; acc[3][3] += a.w * b.w;
        }
        __syncthreads();
    }

#pragma unroll
    for (int i = 0; i < 4; i++) {
        int rr = m0 + ty * 4 + i;
        if (rr < end) {
            float4 o;
            o.x = acc[i][0]; o.y = acc[i][1]; o.z = acc[i][2]; o.w = acc[i][3];
            *(float4*)&g_y[(size_t)rr * HID + n0 + tx * 4] = o;
        }
    }
}

// ---------------- combine: out[t] = p0*y[pos0] + p1*y[pos1] ----------------
__global__ void combine_kernel(float* __restrict__ out) {
    const int HC  = HID / 4;
    int idx = blockIdx.x * blockDim.x + threadIdx.x;
    if (idx >= N_TOKENS * HC) return;
    int t = idx / HC;
    int c = idx % HC;
    float p0 = g_topk_prob[2 * t];
    float p1 = g_topk_prob[2 * t + 1];
    int pos0 = g_posof[2 * t];
    int pos1 = g_posof[2 * t + 1];
    float4 y0 = *(const float4*)&g_y[(size_t)pos0 * HID + c * 4];
    float4 y1 = *(const float4*)&g_y[(size_t)pos1 * HID + c * 4];
    float4 o;
    o.x = p0 * y0.x + p1 * y1.x;
    o.y = p0 * y0.y + p1 * y1.y;
    o.z = p0 * y0.z + p1 * y1.z;
    o.w = p0 * y0.w + p1 * y1.w;
    *(float4*)&out[(size_t)t * HID + c * 4] = o;
}

// ---------------- launch ----------------
extern "C" void kernel_launch(void* const* d_in, const int* in_sizes, int n_in,
                              void* d_out, int out_size) {
    const float* x  = (const float*)d_in[0];
    const float* rw = (const float*)d_in[1];
    const float* w1 = (const float*)d_in[2];
    const float* w2 = (const float*)d_in[3];
    // d_in[4] = top_k (fixed at 2)
    float* out = (float*)d_out;

    init_kernel<<<1, 32>>>();
    router_kernel<<<N_TOKENS, 256>>>(x, rw);
    offsets_kernel<<<1, 1>>>();
    scatter_kernel<<<NPAIR / 256, 256>>>();
    gemm1_kernel<<<dim3(FFN / 64, NPAIR / 64, NEXP), 256>>>(x, w1);
    gemm2_kernel<<<dim3(HID / 64, NPAIR / 64, NEXP), 256>>>(w2);
    combine_kernel<<<(N_TOKENS * (HID / 4) + 255) / 256, 256>>>(out);
}